// round 1
// baseline (speedup 1.0000x reference)
#include <cuda_runtime.h>
#include <math.h>

#define B_  4
#define S_  2048
#define D_  1024
#define H_  16
#define HD_ 64
#define NROW (B_*S_)          // 8192

// ---------------- scratch (static device globals; no allocation) ------------
__device__ float g_q  [NROW * D_];
__device__ float g_k  [NROW * D_];
__device__ float g_v  [NROW * D_];
__device__ float g_ctx[NROW * D_];

// ---------------------------------------------------------------------------
// GEMM: C[M,N] = A[M,K] @ B[K,N] (+ bias[N]).  128x128 tile, BK=8,
// 256 threads, 8x8 register blocking, float4 global+smem traffic.
// M,N,K assumed multiples of 128/128/8 (true here: 8192/1024/1024).
// ---------------------------------------------------------------------------
__global__ __launch_bounds__(256) void gemm128(const float* __restrict__ A,
                                               const float* __restrict__ Bm,
                                               const float* __restrict__ bias,
                                               float* __restrict__ C,
                                               int M, int N, int K)
{
    __shared__ float Ast[8 * 128];   // transposed A tile: Ast[k][m]
    __shared__ float Bs [8 * 128];   // B tile:            Bs[k][n]

    const int tid = threadIdx.x;
    const int RM = blockIdx.y * 128;
    const int CN = blockIdx.x * 128;
    const int ty = tid >> 4;          // 0..15
    const int tx = tid & 15;          // 0..15

    float acc[8][8];
#pragma unroll
    for (int i = 0; i < 8; i++)
#pragma unroll
        for (int j = 0; j < 8; j++) acc[i][j] = 0.f;

    const int ar = tid >> 1;          // 0..127  (A tile row)
    const int ac = (tid & 1) * 4;     // 0 or 4  (A tile col base)
    const int br = tid >> 5;          // 0..7    (B tile row)
    const int bc = (tid & 31) * 4;    // 0..124  (B tile col base)

    const float* Aptr = A + (size_t)(RM + ar) * K + ac;
    const float* Bptr = Bm + (size_t)br * N + CN + bc;

    for (int k0 = 0; k0 < K; k0 += 8) {
        float4 a4 = *(const float4*)(Aptr + k0);
        float4 b4 = *(const float4*)(Bptr + (size_t)k0 * N);
        Ast[(ac + 0) * 128 + ar] = a4.x;
        Ast[(ac + 1) * 128 + ar] = a4.y;
        Ast[(ac + 2) * 128 + ar] = a4.z;
        Ast[(ac + 3) * 128 + ar] = a4.w;
        *(float4*)&Bs[br * 128 + bc] = b4;
        __syncthreads();

#pragma unroll
        for (int kk = 0; kk < 8; kk++) {
            float a[8], b[8];
            *(float4*)&a[0] = *(float4*)&Ast[kk * 128 + ty * 8];
            *(float4*)&a[4] = *(float4*)&Ast[kk * 128 + ty * 8 + 4];
            *(float4*)&b[0] = *(float4*)&Bs [kk * 128 + tx * 8];
            *(float4*)&b[4] = *(float4*)&Bs [kk * 128 + tx * 8 + 4];
#pragma unroll
            for (int i = 0; i < 8; i++)
#pragma unroll
                for (int j = 0; j < 8; j++)
                    acc[i][j] = fmaf(a[i], b[j], acc[i][j]);
        }
        __syncthreads();
    }

    // epilogue
#pragma unroll
    for (int i = 0; i < 8; i++) {
        const int row = RM + ty * 8 + i;
        float* cp = C + (size_t)row * N + CN + tx * 8;
        float4 o0, o1;
        if (bias) {
            const float* bp = bias + CN + tx * 8;
            o0 = make_float4(acc[i][0] + bp[0], acc[i][1] + bp[1],
                             acc[i][2] + bp[2], acc[i][3] + bp[3]);
            o1 = make_float4(acc[i][4] + bp[4], acc[i][5] + bp[5],
                             acc[i][6] + bp[6], acc[i][7] + bp[7]);
        } else {
            o0 = make_float4(acc[i][0], acc[i][1], acc[i][2], acc[i][3]);
            o1 = make_float4(acc[i][4], acc[i][5], acc[i][6], acc[i][7]);
        }
        *(float4*)(cp)     = o0;
        *(float4*)(cp + 4) = o1;
    }
}

// ---------------------------------------------------------------------------
// Flash attention (causal).  One CTA per (b, h, 64-row q block), 256 threads.
// q/k/v layout: [B*S, D] with head h occupying cols h*64..h*64+63.
// Online softmax; only k-blocks j <= qb processed (causal).
// Dynamic smem layout (floats):
//   Qt[64][64] (Qt[e][r]) | Kt[64][64] (Kt[e][c]) | Vs[64][64] (Vs[s][c]) |
//   Ss[64][65] | m[64] | l[64] | sc[64]
// ---------------------------------------------------------------------------
#define FSM_FLOATS (3 * 4096 + 64 * 65 + 3 * 64)
#define FSM_BYTES  (FSM_FLOATS * 4)

__global__ __launch_bounds__(256) void flash_attn(const float* __restrict__ Q,
                                                  const float* __restrict__ K,
                                                  const float* __restrict__ V,
                                                  float* __restrict__ O)
{
    extern __shared__ float sm[];
    float* Qt  = sm;
    float* Kt  = Qt + 4096;
    float* Vs  = Kt + 4096;
    float* Ss  = Vs + 4096;           // pitch 65
    float* m_s = Ss + 64 * 65;
    float* l_s = m_s + 64;
    float* sc_s = l_s + 64;

    const int tid = threadIdx.x;
    const int qb = blockIdx.x;
    const int h  = blockIdx.y;
    const int b  = blockIdx.z;
    const int qbase = qb * 64;

    const int lr  = tid >> 2;         // 0..63  (loader row)
    const int lc0 = (tid & 3) * 16;   // 0,16,32,48

    const int tr = tid >> 4;          // 0..15
    const int tc = tid & 15;          // 0..15
    const int r0 = tr * 4;
    const int c0 = tc * 4;

    const float scale = 1.0f / sqrtf((float)HD_);   // 0.125

    // ---- load Q tile (scaled), transposed into Qt[e][r] ----
    {
        const float* qg = Q + ((size_t)(b * S_ + qbase + lr)) * D_ + h * HD_ + lc0;
#pragma unroll
        for (int ch = 0; ch < 4; ch++) {
            float4 v4 = *(const float4*)(qg + ch * 4);
            int c = lc0 + ch * 4;
            Qt[(c + 0) * 64 + lr] = v4.x * scale;
            Qt[(c + 1) * 64 + lr] = v4.y * scale;
            Qt[(c + 2) * 64 + lr] = v4.z * scale;
            Qt[(c + 3) * 64 + lr] = v4.w * scale;
        }
    }
    if (tid < 64) { m_s[tid] = -INFINITY; l_s[tid] = 0.f; }

    float o[4][4];
#pragma unroll
    for (int i = 0; i < 4; i++)
#pragma unroll
        for (int j = 0; j < 4; j++) o[i][j] = 0.f;

    for (int jb = 0; jb <= qb; jb++) {
        const int kbase = jb * 64;
        __syncthreads();   // prior iteration consumers done (and Q/m/l init on iter 0)

        // ---- load K tile transposed, V tile row-major ----
        {
            const float* kg = K + ((size_t)(b * S_ + kbase + lr)) * D_ + h * HD_ + lc0;
            const float* vg = V + ((size_t)(b * S_ + kbase + lr)) * D_ + h * HD_ + lc0;
#pragma unroll
            for (int ch = 0; ch < 4; ch++) {
                float4 k4 = *(const float4*)(kg + ch * 4);
                int c = lc0 + ch * 4;
                Kt[(c + 0) * 64 + lr] = k4.x;
                Kt[(c + 1) * 64 + lr] = k4.y;
                Kt[(c + 2) * 64 + lr] = k4.z;
                Kt[(c + 3) * 64 + lr] = k4.w;
                *(float4*)&Vs[lr * 64 + c] = *(const float4*)(vg + ch * 4);
            }
        }
        __syncthreads();

        // ---- S = (Q*scale) @ K^T  (each thread 4x4) ----
        float sacc[4][4];
#pragma unroll
        for (int i = 0; i < 4; i++)
#pragma unroll
            for (int j = 0; j < 4; j++) sacc[i][j] = 0.f;

#pragma unroll 8
        for (int e = 0; e < 64; e++) {
            float qa[4], ka[4];
            *(float4*)qa = *(float4*)&Qt[e * 64 + r0];
            *(float4*)ka = *(float4*)&Kt[e * 64 + c0];
#pragma unroll
            for (int i = 0; i < 4; i++)
#pragma unroll
                for (int j = 0; j < 4; j++)
                    sacc[i][j] = fmaf(qa[i], ka[j], sacc[i][j]);
        }

        const bool diag = (jb == qb);
#pragma unroll
        for (int i = 0; i < 4; i++)
#pragma unroll
            for (int j = 0; j < 4; j++) {
                int rr = r0 + i, cc = c0 + j;
                float sv = sacc[i][j];
                if (diag && cc > rr) sv = -INFINITY;
                Ss[rr * 65 + cc] = sv;
            }
        __syncthreads();

        // ---- online softmax: one thread per row ----
        if (tid < 64) {
            float* row = &Ss[tid * 65];
            float m_old = m_s[tid];
            float mx = m_old;
#pragma unroll 8
            for (int c = 0; c < 64; c++) mx = fmaxf(mx, row[c]);
            float sum = 0.f;
#pragma unroll 8
            for (int c = 0; c < 64; c++) {
                float p = __expf(row[c] - mx);
                row[c] = p;
                sum += p;
            }
            float sc = __expf(m_old - mx);   // 0 on first block (m_old = -inf)
            sc_s[tid] = sc;
            l_s[tid] = l_s[tid] * sc + sum;
            m_s[tid] = mx;
        }
        __syncthreads();

        // ---- rescale accumulator, then O += P @ V ----
        float rs[4];
#pragma unroll
        for (int i = 0; i < 4; i++) rs[i] = sc_s[r0 + i];
#pragma unroll
        for (int i = 0; i < 4; i++)
#pragma unroll
            for (int j = 0; j < 4; j++) o[i][j] *= rs[i];

#pragma unroll 8
        for (int s = 0; s < 64; s++) {
            float p[4], va[4];
#pragma unroll
            for (int i = 0; i < 4; i++) p[i] = Ss[(r0 + i) * 65 + s];
            *(float4*)va = *(float4*)&Vs[s * 64 + c0];
#pragma unroll
            for (int i = 0; i < 4; i++)
#pragma unroll
                for (int j = 0; j < 4; j++)
                    o[i][j] = fmaf(p[i], va[j], o[i][j]);
        }
    }

    // ---- normalize and write ctx ----
    float inv[4];
#pragma unroll
    for (int i = 0; i < 4; i++) inv[i] = 1.0f / l_s[r0 + i];
#pragma unroll
    for (int i = 0; i < 4; i++) {
        float* op = O + ((size_t)(b * S_ + qbase + r0 + i)) * D_ + h * HD_ + c0;
        *(float4*)op = make_float4(o[i][0] * inv[i], o[i][1] * inv[i],
                                   o[i][2] * inv[i], o[i][3] * inv[i]);
    }
}

// ---------------------------------------------------------------------------
extern "C" void kernel_launch(void* const* d_in, const int* in_sizes, int n_in,
                              void* d_out, int out_size)
{
    const float* x  = (const float*)d_in[0];
    const float* Wq = (const float*)d_in[1];
    const float* Wk = (const float*)d_in[2];
    const float* Wv = (const float*)d_in[3];
    const float* Wo = (const float*)d_in[4];
    const float* bo = (const float*)d_in[5];
    float* out = (float*)d_out;

    float *q, *k, *v, *ctx;
    cudaGetSymbolAddress((void**)&q,   g_q);
    cudaGetSymbolAddress((void**)&k,   g_k);
    cudaGetSymbolAddress((void**)&v,   g_v);
    cudaGetSymbolAddress((void**)&ctx, g_ctx);

    cudaFuncSetAttribute(flash_attn, cudaFuncAttributeMaxDynamicSharedMemorySize,
                         FSM_BYTES);

    dim3 gg(D_ / 128, NROW / 128);   // (8, 64)
    gemm128<<<gg, 256>>>(x, Wq, nullptr, q, NROW, D_, D_);
    gemm128<<<gg, 256>>>(x, Wk, nullptr, k, NROW, D_, D_);
    gemm128<<<gg, 256>>>(x, Wv, nullptr, v, NROW, D_, D_);

    dim3 fg(S_ / 64, H_, B_);        // (32, 16, 4) = 2048 CTAs
    flash_attn<<<fg, 256, FSM_BYTES>>>(q, k, v, ctx);

    gemm128<<<gg, 256>>>(ctx, Wo, bo, out, NROW, D_, D_);
}

// round 5
// speedup vs baseline: 1.6808x; 1.6808x over previous
#include <cuda_runtime.h>
#include <cuda_bf16.h>
#include <math.h>
#include <stdint.h>

#define B_  4
#define S_  2048
#define D_  1024
#define H_  16
#define HD_ 64
#define NROW (B_*S_)          // 8192

#define TK      64            // K elems per chunk (64 bf16 = 128B = SW128 atom row)
#define NCHUNK  (D_/TK)       // 16
#define TILE_B  16384         // bytes per 128-row x 128B tile

// ---------------- scratch (static device globals; no allocation) ------------
__device__ __align__(16) float g_q  [NROW * D_];
__device__ __align__(16) float g_k  [NROW * D_];
__device__ __align__(16) float g_v  [NROW * D_];
__device__ __align__(16) float g_ctx[NROW * D_];

// tiled+swizzled bf16 hi/lo images (SMEM-layout-identical, straight-copy loads)
__device__ __align__(128) __nv_bfloat16 g_xh[NROW * D_];
__device__ __align__(128) __nv_bfloat16 g_xl[NROW * D_];
__device__ __align__(128) __nv_bfloat16 g_ch[NROW * D_];
__device__ __align__(128) __nv_bfloat16 g_cl[NROW * D_];
__device__ __align__(128) __nv_bfloat16 g_wqh[D_ * D_];
__device__ __align__(128) __nv_bfloat16 g_wql[D_ * D_];
__device__ __align__(128) __nv_bfloat16 g_wkh[D_ * D_];
__device__ __align__(128) __nv_bfloat16 g_wkl[D_ * D_];
__device__ __align__(128) __nv_bfloat16 g_wvh[D_ * D_];
__device__ __align__(128) __nv_bfloat16 g_wvl[D_ * D_];
__device__ __align__(128) __nv_bfloat16 g_woh[D_ * D_];
__device__ __align__(128) __nv_bfloat16 g_wol[D_ * D_];

// ---------------------------- helpers ---------------------------------------
__device__ __forceinline__ uint32_t smem_u32(const void* p) {
    uint32_t a;
    asm("{ .reg .u64 t; cvta.to.shared.u64 t, %1; cvt.u32.u64 %0, t; }"
        : "=r"(a) : "l"(p));
    return a;
}
__host__ __device__ __forceinline__ uint32_t swz128(uint32_t o) {
    return o ^ ((o >> 3) & 0x70);
}
__device__ __forceinline__ void cp16(uint32_t dst, const void* src) {
    asm volatile("cp.async.cg.shared.global [%0], [%1], 16;"
                 :: "r"(dst), "l"(src) : "memory");
}
__device__ __forceinline__ void cp_commit() {
    asm volatile("cp.async.commit_group;" ::: "memory");
}
__device__ __forceinline__ void cp_wait0() {
    asm volatile("cp.async.wait_group 0;" ::: "memory");
}
__device__ __forceinline__ void ldm_x4(uint32_t* r, uint32_t addr) {
    asm volatile("ldmatrix.sync.aligned.m8n8.x4.shared.b16 {%0,%1,%2,%3}, [%4];"
                 : "=r"(r[0]), "=r"(r[1]), "=r"(r[2]), "=r"(r[3]) : "r"(addr));
}
__device__ __forceinline__ void mma16816(float* c, const uint32_t* a,
                                         const uint32_t* b) {
    asm volatile(
        "mma.sync.aligned.m16n8k16.row.col.f32.bf16.bf16.f32 "
        "{%0,%1,%2,%3}, {%4,%5,%6,%7}, {%8,%9}, {%0,%1,%2,%3};"
        : "+f"(c[0]), "+f"(c[1]), "+f"(c[2]), "+f"(c[3])
        : "r"(a[0]), "r"(a[1]), "r"(a[2]), "r"(a[3]), "r"(b[0]), "r"(b[1]));
}

// ---------------------------------------------------------------------------
// Conversion: fp32 activations [8192,1024] -> tiled/swizzled bf16 hi/lo.
// Tile (rb, kc): 128 rows x 64 K-elems, SW128 swizzled, 16KB contiguous.
// ---------------------------------------------------------------------------
__global__ __launch_bounds__(256) void conv_act(const float* __restrict__ in,
                                                __nv_bfloat16* __restrict__ oh,
                                                __nv_bfloat16* __restrict__ ol)
{
    int idx = blockIdx.x * 256 + threadIdx.x;   // 1,048,576 = rows * 128
    int R  = idx >> 7, cb = idx & 127;
    int rb = R >> 7,  r  = R & 127;
    int kc = cb >> 3, cc = cb & 7;
    const float* p = in + (size_t)R * D_ + cb * 8;
    float4 a = *(const float4*)p;
    float4 b = *(const float4*)(p + 4);
    float v[8] = {a.x, a.y, a.z, a.w, b.x, b.y, b.z, b.w};
    union { __nv_bfloat16 h[8]; uint4 u; } uh, ul;
#pragma unroll
    for (int j = 0; j < 8; j++) {
        __nv_bfloat16 hb = __float2bfloat16(v[j]);
        uh.h[j] = hb;
        ul.h[j] = __float2bfloat16(v[j] - __bfloat162float(hb));
    }
    uint32_t off = (uint32_t)(rb * NCHUNK + kc) * TILE_B + swz128(r * 128 + cc * 16);
    *(uint4*)((char*)oh + off) = uh.u;
    *(uint4*)((char*)ol + off) = ul.u;
}

// Weights: W[K=1024, N=1024] -> transposed tiled/swizzled bf16 hi/lo (Wt[n,k]).
__global__ __launch_bounds__(256) void conv_w(const float* __restrict__ W,
                                              __nv_bfloat16* __restrict__ oh,
                                              __nv_bfloat16* __restrict__ ol)
{
    int idx = blockIdx.x * 256 + threadIdx.x;   // 131072 = 1024(n) * 128(kb)
    int n  = idx & 1023, kb = idx >> 10;
    float v[8];
#pragma unroll
    for (int j = 0; j < 8; j++) v[j] = W[(size_t)(kb * 8 + j) * D_ + n];
    union { __nv_bfloat16 h[8]; uint4 u; } uh, ul;
#pragma unroll
    for (int j = 0; j < 8; j++) {
        __nv_bfloat16 hb = __float2bfloat16(v[j]);
        uh.h[j] = hb;
        ul.h[j] = __float2bfloat16(v[j] - __bfloat162float(hb));
    }
    int tb = n >> 7, r = n & 127, kc = kb >> 3, cc = kb & 7;
    uint32_t off = (uint32_t)(tb * NCHUNK + kc) * TILE_B + swz128(r * 128 + cc * 16);
    *(uint4*)((char*)oh + off) = uh.u;
    *(uint4*)((char*)ol + off) = ul.u;
}

// ---------------------------------------------------------------------------
// mma.sync GEMM: C[8192,1024] = A @ B^T, split bf16 (hi/lo, 3 MMA passes).
// CTA tile 128x128, 8 warps (2m x 4n), warp tile 64x32. K chunked by 64,
// smem tiles are SW128-swizzled images straight-copied from gmem, read back
// with ldmatrix at swizzled addresses.
// ---------------------------------------------------------------------------
#define GSM_BYTES (4 * TILE_B)   // 65536

__global__ __launch_bounds__(256, 2) void gemm_mma(
    const __nv_bfloat16* __restrict__ Ah, const __nv_bfloat16* __restrict__ Al,
    const __nv_bfloat16* __restrict__ Bh, const __nv_bfloat16* __restrict__ Bl,
    const float* __restrict__ bias, float* __restrict__ C)
{
    extern __shared__ char sm[];
    const uint32_t SA_H = smem_u32(sm);
    const uint32_t SA_L = SA_H + TILE_B;
    const uint32_t SB_H = SA_L + TILE_B;
    const uint32_t SB_L = SB_H + TILE_B;

    const int tid  = threadIdx.x;
    const int wid  = tid >> 5;
    const int lane = tid & 31;
    const int wm   = wid >> 2;          // 0..1  (m half)
    const int wn   = wid & 3;           // 0..3  (n quarter)
    const int tb   = blockIdx.x;        // N tile
    const int rb   = blockIdx.y;        // M tile

    float acc[4][4][4];
#pragma unroll
    for (int i = 0; i < 4; i++)
#pragma unroll
        for (int j = 0; j < 4; j++)
#pragma unroll
            for (int r = 0; r < 4; r++) acc[i][j][r] = 0.f;

    const char* gAh = (const char*)Ah + (size_t)rb * NCHUNK * TILE_B;
    const char* gAl = (const char*)Al + (size_t)rb * NCHUNK * TILE_B;
    const char* gBh = (const char*)Bh + (size_t)tb * NCHUNK * TILE_B;
    const char* gBl = (const char*)Bl + (size_t)tb * NCHUNK * TILE_B;

    // per-thread ldmatrix address components (within-tile, before swizzle)
    const int a_row  = wm * 64 + (lane & 15);          // + i*16
    const int a_cb0  = (lane >> 4) * 16;               // + ks*32
    const int b_idx  = lane >> 3;                      // 0..3
    const int b_row  = wn * 32 + ((b_idx >> 1) * 8) + (lane & 7);  // + jp*16
    const int b_cb0  = (b_idx & 1) * 16;               // + ks*32

    for (int c = 0; c < NCHUNK; c++) {
        if (c) __syncthreads();        // smem consumers of prev chunk done
        const uint32_t cofs = (uint32_t)c * TILE_B;
#pragma unroll
        for (int i = tid; i < 1024; i += 256) {
            cp16(SA_H + i * 16, gAh + cofs + i * 16);
            cp16(SA_L + i * 16, gAl + cofs + i * 16);
            cp16(SB_H + i * 16, gBh + cofs + i * 16);
            cp16(SB_L + i * 16, gBl + cofs + i * 16);
        }
        cp_commit();
        cp_wait0();
        __syncthreads();

#pragma unroll
        for (int ks = 0; ks < 4; ks++) {
            uint32_t ah[4][4], al[4][4], bh[4][2], bl[4][2];
            const uint32_t acb = ks * 32 + a_cb0;
            const uint32_t bcb = ks * 32 + b_cb0;
#pragma unroll
            for (int i = 0; i < 4; i++) {
                uint32_t off = swz128((uint32_t)(a_row + i * 16) * 128 + acb);
                ldm_x4(ah[i], SA_H + off);
                ldm_x4(al[i], SA_L + off);
            }
#pragma unroll
            for (int jp = 0; jp < 2; jp++) {
                uint32_t off = swz128((uint32_t)(b_row + jp * 16) * 128 + bcb);
                uint32_t th[4], tl[4];
                ldm_x4(th, SB_H + off);
                ldm_x4(tl, SB_L + off);
                bh[jp * 2 + 0][0] = th[0]; bh[jp * 2 + 0][1] = th[1];
                bh[jp * 2 + 1][0] = th[2]; bh[jp * 2 + 1][1] = th[3];
                bl[jp * 2 + 0][0] = tl[0]; bl[jp * 2 + 0][1] = tl[1];
                bl[jp * 2 + 1][0] = tl[2]; bl[jp * 2 + 1][1] = tl[3];
            }
#pragma unroll
            for (int i = 0; i < 4; i++)
#pragma unroll
                for (int j = 0; j < 4; j++) {
                    mma16816(acc[i][j], ah[i], bh[j]);
                    mma16816(acc[i][j], ah[i], bl[j]);
                    mma16816(acc[i][j], al[i], bh[j]);
                }
        }
    }

    // ---- epilogue ----
    const int row0 = rb * 128 + wm * 64 + (lane >> 2);
    const int col0 = tb * 128 + wn * 32 + (lane & 3) * 2;
#pragma unroll
    for (int i = 0; i < 4; i++)
#pragma unroll
        for (int j = 0; j < 4; j++) {
            const int cc = col0 + j * 8;
            float b0 = 0.f, b1 = 0.f;
            if (bias) { b0 = bias[cc]; b1 = bias[cc + 1]; }
            float* p0 = C + (size_t)(row0 + i * 16) * D_ + cc;
            float* p1 = C + (size_t)(row0 + i * 16 + 8) * D_ + cc;
            *(float2*)p0 = make_float2(acc[i][j][0] + b0, acc[i][j][1] + b1);
            *(float2*)p1 = make_float2(acc[i][j][2] + b0, acc[i][j][3] + b1);
        }
}

// ---------------------------------------------------------------------------
// Flash attention (causal) — unchanged from R0 (known-correct).
// ---------------------------------------------------------------------------
#define FSM_FLOATS (3 * 4096 + 64 * 65 + 3 * 64)
#define FSM_BYTES  (FSM_FLOATS * 4)

__global__ __launch_bounds__(256) void flash_attn(const float* __restrict__ Q,
                                                  const float* __restrict__ K,
                                                  const float* __restrict__ V,
                                                  float* __restrict__ O)
{
    extern __shared__ float smf[];
    float* Qt  = smf;
    float* Kt  = Qt + 4096;
    float* Vs  = Kt + 4096;
    float* Ss  = Vs + 4096;           // pitch 65
    float* m_s = Ss + 64 * 65;
    float* l_s = m_s + 64;
    float* sc_s = l_s + 64;

    const int tid = threadIdx.x;
    const int qb = blockIdx.x;
    const int h  = blockIdx.y;
    const int b  = blockIdx.z;
    const int qbase = qb * 64;

    const int lr  = tid >> 2;
    const int lc0 = (tid & 3) * 16;

    const int tr = tid >> 4;
    const int tc = tid & 15;
    const int r0 = tr * 4;
    const int c0 = tc * 4;

    const float scale = 1.0f / sqrtf((float)HD_);

    {
        const float* qg = Q + ((size_t)(b * S_ + qbase + lr)) * D_ + h * HD_ + lc0;
#pragma unroll
        for (int ch = 0; ch < 4; ch++) {
            float4 v4 = *(const float4*)(qg + ch * 4);
            int c = lc0 + ch * 4;
            Qt[(c + 0) * 64 + lr] = v4.x * scale;
            Qt[(c + 1) * 64 + lr] = v4.y * scale;
            Qt[(c + 2) * 64 + lr] = v4.z * scale;
            Qt[(c + 3) * 64 + lr] = v4.w * scale;
        }
    }
    if (tid < 64) { m_s[tid] = -INFINITY; l_s[tid] = 0.f; }

    float o[4][4];
#pragma unroll
    for (int i = 0; i < 4; i++)
#pragma unroll
        for (int j = 0; j < 4; j++) o[i][j] = 0.f;

    for (int jb = 0; jb <= qb; jb++) {
        const int kbase = jb * 64;
        __syncthreads();

        {
            const float* kg = K + ((size_t)(b * S_ + kbase + lr)) * D_ + h * HD_ + lc0;
            const float* vg = V + ((size_t)(b * S_ + kbase + lr)) * D_ + h * HD_ + lc0;
#pragma unroll
            for (int ch = 0; ch < 4; ch++) {
                float4 k4 = *(const float4*)(kg + ch * 4);
                int c = lc0 + ch * 4;
                Kt[(c + 0) * 64 + lr] = k4.x;
                Kt[(c + 1) * 64 + lr] = k4.y;
                Kt[(c + 2) * 64 + lr] = k4.z;
                Kt[(c + 3) * 64 + lr] = k4.w;
                *(float4*)&Vs[lr * 64 + c] = *(const float4*)(vg + ch * 4);
            }
        }
        __syncthreads();

        float sacc[4][4];
#pragma unroll
        for (int i = 0; i < 4; i++)
#pragma unroll
            for (int j = 0; j < 4; j++) sacc[i][j] = 0.f;

#pragma unroll 8
        for (int e = 0; e < 64; e++) {
            float qa[4], ka[4];
            *(float4*)qa = *(float4*)&Qt[e * 64 + r0];
            *(float4*)ka = *(float4*)&Kt[e * 64 + c0];
#pragma unroll
            for (int i = 0; i < 4; i++)
#pragma unroll
                for (int j = 0; j < 4; j++)
                    sacc[i][j] = fmaf(qa[i], ka[j], sacc[i][j]);
        }

        const bool diag = (jb == qb);
#pragma unroll
        for (int i = 0; i < 4; i++)
#pragma unroll
            for (int j = 0; j < 4; j++) {
                int rr = r0 + i, cc = c0 + j;
                float sv = sacc[i][j];
                if (diag && cc > rr) sv = -INFINITY;
                Ss[rr * 65 + cc] = sv;
            }
        __syncthreads();

        if (tid < 64) {
            float* row = &Ss[tid * 65];
            float m_old = m_s[tid];
            float mx = m_old;
#pragma unroll 8
            for (int c = 0; c < 64; c++) mx = fmaxf(mx, row[c]);
            float sum = 0.f;
#pragma unroll 8
            for (int c = 0; c < 64; c++) {
                float p = __expf(row[c] - mx);
                row[c] = p;
                sum += p;
            }
            float sc = __expf(m_old - mx);
            sc_s[tid] = sc;
            l_s[tid] = l_s[tid] * sc + sum;
            m_s[tid] = mx;
        }
        __syncthreads();

        float rs[4];
#pragma unroll
        for (int i = 0; i < 4; i++) rs[i] = sc_s[r0 + i];
#pragma unroll
        for (int i = 0; i < 4; i++)
#pragma unroll
            for (int j = 0; j < 4; j++) o[i][j] *= rs[i];

#pragma unroll 8
        for (int s = 0; s < 64; s++) {
            float p[4], va[4];
#pragma unroll
            for (int i = 0; i < 4; i++) p[i] = Ss[(r0 + i) * 65 + s];
            *(float4*)va = *(float4*)&Vs[s * 64 + c0];
#pragma unroll
            for (int i = 0; i < 4; i++)
#pragma unroll
                for (int j = 0; j < 4; j++)
                    o[i][j] = fmaf(p[i], va[j], o[i][j]);
        }
    }

    float inv[4];
#pragma unroll
    for (int i = 0; i < 4; i++) inv[i] = 1.0f / l_s[r0 + i];
#pragma unroll
    for (int i = 0; i < 4; i++) {
        float* op = O + ((size_t)(b * S_ + qbase + r0 + i)) * D_ + h * HD_ + c0;
        *(float4*)op = make_float4(o[i][0] * inv[i], o[i][1] * inv[i],
                                   o[i][2] * inv[i], o[i][3] * inv[i]);
    }
}

// ---------------------------------------------------------------------------
extern "C" void kernel_launch(void* const* d_in, const int* in_sizes, int n_in,
                              void* d_out, int out_size)
{
    const float* x  = (const float*)d_in[0];
    const float* Wq = (const float*)d_in[1];
    const float* Wk = (const float*)d_in[2];
    const float* Wv = (const float*)d_in[3];
    const float* Wo = (const float*)d_in[4];
    const float* bo = (const float*)d_in[5];
    float* out = (float*)d_out;

    float *q, *k, *v, *ctx;
    __nv_bfloat16 *xh, *xl, *ch, *cl;
    __nv_bfloat16 *wqh, *wql, *wkh, *wkl, *wvh, *wvl, *woh, *wol;
    cudaGetSymbolAddress((void**)&q,   g_q);
    cudaGetSymbolAddress((void**)&k,   g_k);
    cudaGetSymbolAddress((void**)&v,   g_v);
    cudaGetSymbolAddress((void**)&ctx, g_ctx);
    cudaGetSymbolAddress((void**)&xh,  g_xh);
    cudaGetSymbolAddress((void**)&xl,  g_xl);
    cudaGetSymbolAddress((void**)&ch,  g_ch);
    cudaGetSymbolAddress((void**)&cl,  g_cl);
    cudaGetSymbolAddress((void**)&wqh, g_wqh);
    cudaGetSymbolAddress((void**)&wql, g_wql);
    cudaGetSymbolAddress((void**)&wkh, g_wkh);
    cudaGetSymbolAddress((void**)&wkl, g_wkl);
    cudaGetSymbolAddress((void**)&wvh, g_wvh);
    cudaGetSymbolAddress((void**)&wvl, g_wvl);
    cudaGetSymbolAddress((void**)&woh, g_woh);
    cudaGetSymbolAddress((void**)&wol, g_wol);

    cudaFuncSetAttribute(gemm_mma, cudaFuncAttributeMaxDynamicSharedMemorySize,
                         GSM_BYTES);
    cudaFuncSetAttribute(flash_attn, cudaFuncAttributeMaxDynamicSharedMemorySize,
                         FSM_BYTES);

    // conversions
    conv_act<<<4096, 256>>>(x, xh, xl);
    conv_w<<<512, 256>>>(Wq, wqh, wql);
    conv_w<<<512, 256>>>(Wk, wkh, wkl);
    conv_w<<<512, 256>>>(Wv, wvh, wvl);
    conv_w<<<512, 256>>>(Wo, woh, wol);

    dim3 gg(D_ / 128, NROW / 128);   // (8, 64) = 512 CTAs
    gemm_mma<<<gg, 256, GSM_BYTES>>>(xh, xl, wqh, wql, nullptr, q);
    gemm_mma<<<gg, 256, GSM_BYTES>>>(xh, xl, wkh, wkl, nullptr, k);
    gemm_mma<<<gg, 256, GSM_BYTES>>>(xh, xl, wvh, wvl, nullptr, v);

    dim3 fg(S_ / 64, H_, B_);        // (32, 16, 4)
    flash_attn<<<fg, 256, FSM_BYTES>>>(q, k, v, ctx);

    conv_act<<<4096, 256>>>(ctx, ch, cl);
    gemm_mma<<<gg, 256, GSM_BYTES>>>(ch, cl, woh, wol, bo, out);
}

// round 6
// speedup vs baseline: 3.3026x; 1.9649x over previous
#include <cuda_runtime.h>
#include <cuda_bf16.h>
#include <math.h>
#include <stdint.h>

#define B_  4
#define S_  2048
#define D_  1024
#define H_  16
#define HD_ 64
#define NROW (B_*S_)          // 8192

#define TK      64            // K elems per chunk (64 bf16 = 128B = SW128 atom row)
#define NCHUNK  (D_/TK)       // 16
#define TILE_B  16384         // bytes per 128-row x 128B tile

#define QSCALE 0.1803368801111601f   // 0.125 * log2(e)

// ---------------- scratch (static device globals; no allocation) ------------
// tiled+swizzled bf16 hi/lo images (SMEM-layout-identical, straight-copy loads)
__device__ __align__(128) __nv_bfloat16 g_xh[NROW * D_];
__device__ __align__(128) __nv_bfloat16 g_xl[NROW * D_];
__device__ __align__(128) __nv_bfloat16 g_ch[NROW * D_];   // ctx tiled (flash out)
__device__ __align__(128) __nv_bfloat16 g_cl[NROW * D_];
__device__ __align__(128) __nv_bfloat16 g_wqh[D_ * D_];
__device__ __align__(128) __nv_bfloat16 g_wql[D_ * D_];
__device__ __align__(128) __nv_bfloat16 g_wkh[D_ * D_];
__device__ __align__(128) __nv_bfloat16 g_wkl[D_ * D_];
__device__ __align__(128) __nv_bfloat16 g_wvh[D_ * D_];
__device__ __align__(128) __nv_bfloat16 g_wvl[D_ * D_];
__device__ __align__(128) __nv_bfloat16 g_woh[D_ * D_];
__device__ __align__(128) __nv_bfloat16 g_wol[D_ * D_];
// q/k/v row-major bf16 hi/lo ([row, 1024], head h = cols h*64..h*64+63)
__device__ __align__(128) __nv_bfloat16 g_qh[NROW * D_];
__device__ __align__(128) __nv_bfloat16 g_ql[NROW * D_];
__device__ __align__(128) __nv_bfloat16 g_kh[NROW * D_];
__device__ __align__(128) __nv_bfloat16 g_kl[NROW * D_];
__device__ __align__(128) __nv_bfloat16 g_vh[NROW * D_];
__device__ __align__(128) __nv_bfloat16 g_vl[NROW * D_];

// ---------------------------- helpers ---------------------------------------
__device__ __forceinline__ uint32_t smem_u32(const void* p) {
    uint32_t a;
    asm("{ .reg .u64 t; cvta.to.shared.u64 t, %1; cvt.u32.u64 %0, t; }"
        : "=r"(a) : "l"(p));
    return a;
}
__host__ __device__ __forceinline__ uint32_t swz128(uint32_t o) {
    return o ^ ((o >> 3) & 0x70);
}
__device__ __forceinline__ void cp16(uint32_t dst, const void* src) {
    asm volatile("cp.async.cg.shared.global [%0], [%1], 16;"
                 :: "r"(dst), "l"(src) : "memory");
}
__device__ __forceinline__ void cp_commit() {
    asm volatile("cp.async.commit_group;" ::: "memory");
}
__device__ __forceinline__ void cp_wait0() {
    asm volatile("cp.async.wait_group 0;" ::: "memory");
}
__device__ __forceinline__ void cp_wait1() {
    asm volatile("cp.async.wait_group 1;" ::: "memory");
}
__device__ __forceinline__ void ldm_x4(uint32_t* r, uint32_t addr) {
    asm volatile("ldmatrix.sync.aligned.m8n8.x4.shared.b16 {%0,%1,%2,%3}, [%4];"
                 : "=r"(r[0]), "=r"(r[1]), "=r"(r[2]), "=r"(r[3]) : "r"(addr));
}
__device__ __forceinline__ void ldm_x4t(uint32_t* r, uint32_t addr) {
    asm volatile("ldmatrix.sync.aligned.m8n8.x4.trans.shared.b16 {%0,%1,%2,%3}, [%4];"
                 : "=r"(r[0]), "=r"(r[1]), "=r"(r[2]), "=r"(r[3]) : "r"(addr));
}
__device__ __forceinline__ void mma16816(float* c, const uint32_t* a,
                                         const uint32_t* b) {
    asm volatile(
        "mma.sync.aligned.m16n8k16.row.col.f32.bf16.bf16.f32 "
        "{%0,%1,%2,%3}, {%4,%5,%6,%7}, {%8,%9}, {%0,%1,%2,%3};"
        : "+f"(c[0]), "+f"(c[1]), "+f"(c[2]), "+f"(c[3])
        : "r"(a[0]), "r"(a[1]), "r"(a[2]), "r"(a[3]), "r"(b[0]), "r"(b[1]));
}
__device__ __forceinline__ float ex2(float x) {
    float y;
    asm("ex2.approx.ftz.f32 %0, %1;" : "=f"(y) : "f"(x));
    return y;
}
// split (a,b) fp32 into packed bf16 hi and residual-lo words (a in low half)
__device__ __forceinline__ void split2(float a, float b, uint32_t& hi, uint32_t& lo) {
    __nv_bfloat16 ah = __float2bfloat16(a), bh = __float2bfloat16(b);
    __nv_bfloat16 al = __float2bfloat16(a - __bfloat162float(ah));
    __nv_bfloat16 bl = __float2bfloat16(b - __bfloat162float(bh));
    hi = ((uint32_t)__bfloat16_as_ushort(bh) << 16) | __bfloat16_as_ushort(ah);
    lo = ((uint32_t)__bfloat16_as_ushort(bl) << 16) | __bfloat16_as_ushort(al);
}

// ---------------------------------------------------------------------------
// Conversions (unchanged from R4)
// ---------------------------------------------------------------------------
__global__ __launch_bounds__(256) void conv_act(const float* __restrict__ in,
                                                __nv_bfloat16* __restrict__ oh,
                                                __nv_bfloat16* __restrict__ ol)
{
    int idx = blockIdx.x * 256 + threadIdx.x;
    int R  = idx >> 7, cb = idx & 127;
    int rb = R >> 7,  r  = R & 127;
    int kc = cb >> 3, cc = cb & 7;
    const float* p = in + (size_t)R * D_ + cb * 8;
    float4 a = *(const float4*)p;
    float4 b = *(const float4*)(p + 4);
    float v[8] = {a.x, a.y, a.z, a.w, b.x, b.y, b.z, b.w};
    union { __nv_bfloat16 h[8]; uint4 u; } uh, ul;
#pragma unroll
    for (int j = 0; j < 8; j++) {
        __nv_bfloat16 hb = __float2bfloat16(v[j]);
        uh.h[j] = hb;
        ul.h[j] = __float2bfloat16(v[j] - __bfloat162float(hb));
    }
    uint32_t off = (uint32_t)(rb * NCHUNK + kc) * TILE_B + swz128(r * 128 + cc * 16);
    *(uint4*)((char*)oh + off) = uh.u;
    *(uint4*)((char*)ol + off) = ul.u;
}

__global__ __launch_bounds__(256) void conv_w(const float* __restrict__ W,
                                              __nv_bfloat16* __restrict__ oh,
                                              __nv_bfloat16* __restrict__ ol)
{
    int idx = blockIdx.x * 256 + threadIdx.x;
    int n  = idx & 1023, kb = idx >> 10;
    float v[8];
#pragma unroll
    for (int j = 0; j < 8; j++) v[j] = W[(size_t)(kb * 8 + j) * D_ + n];
    union { __nv_bfloat16 h[8]; uint4 u; } uh, ul;
#pragma unroll
    for (int j = 0; j < 8; j++) {
        __nv_bfloat16 hb = __float2bfloat16(v[j]);
        uh.h[j] = hb;
        ul.h[j] = __float2bfloat16(v[j] - __bfloat162float(hb));
    }
    int tb = n >> 7, r = n & 127, kc = kb >> 3, cc = kb & 7;
    uint32_t off = (uint32_t)(tb * NCHUNK + kc) * TILE_B + swz128(r * 128 + cc * 16);
    *(uint4*)((char*)oh + off) = uh.u;
    *(uint4*)((char*)ol + off) = ul.u;
}

// ---------------------------------------------------------------------------
// mma.sync GEMM (R4) with selectable epilogue:
//   Cbh==nullptr -> fp32 out (+bias)
//   Cbh!=nullptr -> bf16 hi/lo out [row,1024], values scaled by oscale
// ---------------------------------------------------------------------------
#define GSM_BYTES (4 * TILE_B)   // 65536

__global__ __launch_bounds__(256, 2) void gemm_mma(
    const __nv_bfloat16* __restrict__ Ah, const __nv_bfloat16* __restrict__ Al,
    const __nv_bfloat16* __restrict__ Bh, const __nv_bfloat16* __restrict__ Bl,
    const float* __restrict__ bias, float* __restrict__ C,
    __nv_bfloat16* __restrict__ Cbh, __nv_bfloat16* __restrict__ Cbl,
    float oscale)
{
    extern __shared__ char sm[];
    const uint32_t SA_H = smem_u32(sm);
    const uint32_t SA_L = SA_H + TILE_B;
    const uint32_t SB_H = SA_L + TILE_B;
    const uint32_t SB_L = SB_H + TILE_B;

    const int tid  = threadIdx.x;
    const int wid  = tid >> 5;
    const int lane = tid & 31;
    const int wm   = wid >> 2;
    const int wn   = wid & 3;
    const int tb   = blockIdx.x;
    const int rb   = blockIdx.y;

    float acc[4][4][4];
#pragma unroll
    for (int i = 0; i < 4; i++)
#pragma unroll
        for (int j = 0; j < 4; j++)
#pragma unroll
            for (int r = 0; r < 4; r++) acc[i][j][r] = 0.f;

    const char* gAh = (const char*)Ah + (size_t)rb * NCHUNK * TILE_B;
    const char* gAl = (const char*)Al + (size_t)rb * NCHUNK * TILE_B;
    const char* gBh = (const char*)Bh + (size_t)tb * NCHUNK * TILE_B;
    const char* gBl = (const char*)Bl + (size_t)tb * NCHUNK * TILE_B;

    const int a_row  = wm * 64 + (lane & 15);
    const int a_cb0  = (lane >> 4) * 16;
    const int b_idx  = lane >> 3;
    const int b_row  = wn * 32 + ((b_idx >> 1) * 8) + (lane & 7);
    const int b_cb0  = (b_idx & 1) * 16;

    for (int c = 0; c < NCHUNK; c++) {
        if (c) __syncthreads();
        const uint32_t cofs = (uint32_t)c * TILE_B;
#pragma unroll
        for (int i = tid; i < 1024; i += 256) {
            cp16(SA_H + i * 16, gAh + cofs + i * 16);
            cp16(SA_L + i * 16, gAl + cofs + i * 16);
            cp16(SB_H + i * 16, gBh + cofs + i * 16);
            cp16(SB_L + i * 16, gBl + cofs + i * 16);
        }
        cp_commit();
        cp_wait0();
        __syncthreads();

#pragma unroll
        for (int ks = 0; ks < 4; ks++) {
            uint32_t ah[4][4], al[4][4], bh[4][2], bl[4][2];
            const uint32_t acb = ks * 32 + a_cb0;
            const uint32_t bcb = ks * 32 + b_cb0;
#pragma unroll
            for (int i = 0; i < 4; i++) {
                uint32_t off = swz128((uint32_t)(a_row + i * 16) * 128 + acb);
                ldm_x4(ah[i], SA_H + off);
                ldm_x4(al[i], SA_L + off);
            }
#pragma unroll
            for (int jp = 0; jp < 2; jp++) {
                uint32_t off = swz128((uint32_t)(b_row + jp * 16) * 128 + bcb);
                uint32_t th[4], tl[4];
                ldm_x4(th, SB_H + off);
                ldm_x4(tl, SB_L + off);
                bh[jp * 2 + 0][0] = th[0]; bh[jp * 2 + 0][1] = th[1];
                bh[jp * 2 + 1][0] = th[2]; bh[jp * 2 + 1][1] = th[3];
                bl[jp * 2 + 0][0] = tl[0]; bl[jp * 2 + 0][1] = tl[1];
                bl[jp * 2 + 1][0] = tl[2]; bl[jp * 2 + 1][1] = tl[3];
            }
#pragma unroll
            for (int i = 0; i < 4; i++)
#pragma unroll
                for (int j = 0; j < 4; j++) {
                    mma16816(acc[i][j], ah[i], bh[j]);
                    mma16816(acc[i][j], ah[i], bl[j]);
                    mma16816(acc[i][j], al[i], bh[j]);
                }
        }
    }

    const int row0 = rb * 128 + wm * 64 + (lane >> 2);
    const int col0 = tb * 128 + wn * 32 + (lane & 3) * 2;
    if (Cbh) {
#pragma unroll
        for (int i = 0; i < 4; i++)
#pragma unroll
            for (int j = 0; j < 4; j++) {
                const int cc = col0 + j * 8;
                uint32_t h0, l0, h1, l1;
                split2(acc[i][j][0] * oscale, acc[i][j][1] * oscale, h0, l0);
                split2(acc[i][j][2] * oscale, acc[i][j][3] * oscale, h1, l1);
                size_t p0 = ((size_t)(row0 + i * 16) * D_ + cc) * 2;
                size_t p1 = ((size_t)(row0 + i * 16 + 8) * D_ + cc) * 2;
                *(uint32_t*)((char*)Cbh + p0) = h0;
                *(uint32_t*)((char*)Cbl + p0) = l0;
                *(uint32_t*)((char*)Cbh + p1) = h1;
                *(uint32_t*)((char*)Cbl + p1) = l1;
            }
    } else {
#pragma unroll
        for (int i = 0; i < 4; i++)
#pragma unroll
            for (int j = 0; j < 4; j++) {
                const int cc = col0 + j * 8;
                float b0 = bias ? bias[cc] : 0.f;
                float b1 = bias ? bias[cc + 1] : 0.f;
                float* p0 = C + (size_t)(row0 + i * 16) * D_ + cc;
                float* p1 = C + (size_t)(row0 + i * 16 + 8) * D_ + cc;
                *(float2*)p0 = make_float2(acc[i][j][0] + b0, acc[i][j][1] + b1);
                *(float2*)p1 = make_float2(acc[i][j][2] + b0, acc[i][j][3] + b1);
            }
    }
}

// ---------------------------------------------------------------------------
// Flash attention on mma.sync, causal, hi/lo split bf16.
// CTA = 128 q rows x (b,h); 8 warps, warp w = rows w*16..w*16+15.
// K/V blocks of 64, double-buffered cp.async.
// smem: QH(16K) QL(16K) | stage[2] x {KH,KL,VH,VL} (8K each) = 96KB
// Writes ctx directly in tiled/swizzled hi/lo format (g_ch/g_cl).
// ---------------------------------------------------------------------------
#define FSMEM (32768 + 65536)

__device__ __forceinline__ void fa_load_stage(
    uint32_t sst, int st, int jb, int tid, size_t rowoff_base,
    const __nv_bfloat16* kh, const __nv_bfloat16* kl,
    const __nv_bfloat16* vh, const __nv_bfloat16* vl)
{
    const int r  = tid >> 2;          // 0..63
    const int u0 = (tid & 3) * 2;     // 0,2,4,6
    const size_t rowoff = rowoff_base + (size_t)(jb * 64 + r) * 2048;
    const uint32_t base = sst + st * 32768;
    const char* s0 = (const char*)kh + rowoff;
    const char* s1 = (const char*)kl + rowoff;
    const char* s2 = (const char*)vh + rowoff;
    const char* s3 = (const char*)vl + rowoff;
#pragma unroll
    for (int uu = 0; uu < 2; uu++) {
        const uint32_t d = swz128(r * 128 + (u0 + uu) * 16);
        const int sb = (u0 + uu) * 16;
        cp16(base + 0 * 8192 + d, s0 + sb);
        cp16(base + 1 * 8192 + d, s1 + sb);
        cp16(base + 2 * 8192 + d, s2 + sb);
        cp16(base + 3 * 8192 + d, s3 + sb);
    }
}

__global__ __launch_bounds__(256) void flash_mma(
    const __nv_bfloat16* __restrict__ qh, const __nv_bfloat16* __restrict__ ql,
    const __nv_bfloat16* __restrict__ kh, const __nv_bfloat16* __restrict__ kl,
    const __nv_bfloat16* __restrict__ vh, const __nv_bfloat16* __restrict__ vl,
    __nv_bfloat16* __restrict__ ch, __nv_bfloat16* __restrict__ cl)
{
    extern __shared__ char sm[];
    const uint32_t SQH = smem_u32(sm);
    const uint32_t SQL = SQH + 16384;
    const uint32_t SST = SQL + 16384;

    const int tid  = threadIdx.x;
    const int w    = tid >> 5;
    const int lane = tid & 31;
    const int qb   = 15 - blockIdx.x;      // big tiles first (load balance)
    const int h    = blockIdx.y;
    const int b    = blockIdx.z;
    const int qbase = qb * 128;            // in-sequence q row base
    const size_t seqoff = ((size_t)b * 2048) * 2048 + (size_t)h * 128; // bytes

    // ---- Q tile load (rows qbase..+127) ----
    {
        const int r  = tid >> 1;
        const int u0 = (tid & 1) * 4;
        const size_t ro = seqoff + (size_t)(qbase + r) * 2048;
        const char* sh = (const char*)qh + ro;
        const char* slo = (const char*)ql + ro;
#pragma unroll
        for (int u = u0; u < u0 + 4; u++) {
            const uint32_t d = swz128(r * 128 + u * 16);
            cp16(SQH + d, sh + u * 16);
            cp16(SQL + d, slo + u * 16);
        }
    }
    cp_commit();

    const int nkb = 2 * qb + 2;
    fa_load_stage(SST, 0, 0, tid, seqoff, kh, kl, vh, vl);
    cp_commit();
    cp_wait0();
    __syncthreads();

    // ---- Q fragments (held in registers for whole kernel) ----
    uint32_t aqh[4][4], aql[4][4];
    {
        const int ar = w * 16 + (lane & 15);
        const int acb = (lane >> 4) * 16;
#pragma unroll
        for (int kt = 0; kt < 4; kt++) {
            const uint32_t off = swz128((uint32_t)ar * 128 + kt * 32 + acb);
            ldm_x4(aqh[kt], SQH + off);
            ldm_x4(aql[kt], SQL + off);
        }
    }

    float o[8][4];
#pragma unroll
    for (int n = 0; n < 8; n++)
#pragma unroll
        for (int r = 0; r < 4; r++) o[n][r] = 0.f;
    float m0 = -INFINITY, m1 = -INFINITY, l0 = 0.f, l1 = 0.f;

    const int wrow0 = qbase + w * 16;      // warp's lowest q row (in-sequence)

    for (int jb = 0; jb < nkb; jb++) {
        if (jb + 1 < nkb) {
            fa_load_stage(SST, (jb + 1) & 1, jb + 1, tid, seqoff, kh, kl, vh, vl);
            cp_commit();
            cp_wait1();
        } else {
            cp_wait0();
        }
        __syncthreads();

        const int kbase = jb * 64;
        if (kbase <= wrow0 + 15) {         // warp has at least one unmasked row
            const uint32_t base = SST + (uint32_t)(jb & 1) * 32768;
            const uint32_t KH = base, KL = base + 8192;
            const uint32_t VH = base + 16384, VL = base + 24576;

            // ---- S = Q K^T (3-pass hi/lo), fragment accumulators ----
            float sacc[8][4];
#pragma unroll
            for (int n = 0; n < 8; n++)
#pragma unroll
                for (int r = 0; r < 4; r++) sacc[n][r] = 0.f;

            const uint32_t krow = ((lane >> 4) & 1) * 8 + (lane & 7);
            const uint32_t kcb  = ((lane >> 3) & 1) * 16;
#pragma unroll
            for (int kt = 0; kt < 4; kt++) {
#pragma unroll
                for (int ntp = 0; ntp < 4; ntp++) {
                    const uint32_t off =
                        swz128((ntp * 16 + krow) * 128 + kt * 32 + kcb);
                    uint32_t bh4[4], bl4[4];
                    ldm_x4(bh4, KH + off);
                    ldm_x4(bl4, KL + off);
                    mma16816(sacc[2 * ntp],     aqh[kt], bh4 + 0);
                    mma16816(sacc[2 * ntp],     aqh[kt], bl4 + 0);
                    mma16816(sacc[2 * ntp],     aql[kt], bh4 + 0);
                    mma16816(sacc[2 * ntp + 1], aqh[kt], bh4 + 2);
                    mma16816(sacc[2 * ntp + 1], aqh[kt], bl4 + 2);
                    mma16816(sacc[2 * ntp + 1], aql[kt], bh4 + 2);
                }
            }

            // ---- causal mask (only near diagonal) ----
            if (kbase + 63 > wrow0) {
                const int rg = wrow0 + (lane >> 2);
#pragma unroll
                for (int nt = 0; nt < 8; nt++) {
                    const int cg = kbase + nt * 8 + (lane & 3) * 2;
                    if (cg     > rg)     sacc[nt][0] = -INFINITY;
                    if (cg + 1 > rg)     sacc[nt][1] = -INFINITY;
                    if (cg     > rg + 8) sacc[nt][2] = -INFINITY;
                    if (cg + 1 > rg + 8) sacc[nt][3] = -INFINITY;
                }
            }

            // ---- online softmax (log2 domain; scale folded into Q) ----
            float nm0 = m0, nm1 = m1;
#pragma unroll
            for (int nt = 0; nt < 8; nt++) {
                nm0 = fmaxf(nm0, fmaxf(sacc[nt][0], sacc[nt][1]));
                nm1 = fmaxf(nm1, fmaxf(sacc[nt][2], sacc[nt][3]));
            }
            nm0 = fmaxf(nm0, __shfl_xor_sync(0xffffffffu, nm0, 1));
            nm0 = fmaxf(nm0, __shfl_xor_sync(0xffffffffu, nm0, 2));
            nm1 = fmaxf(nm1, __shfl_xor_sync(0xffffffffu, nm1, 1));
            nm1 = fmaxf(nm1, __shfl_xor_sync(0xffffffffu, nm1, 2));

            const float sc0 = ex2(m0 - nm0);
            const float sc1 = ex2(m1 - nm1);
            m0 = nm0; m1 = nm1;
            l0 *= sc0; l1 *= sc1;
#pragma unroll
            for (int nt = 0; nt < 8; nt++) {
                o[nt][0] *= sc0; o[nt][1] *= sc0;
                o[nt][2] *= sc1; o[nt][3] *= sc1;
            }

            // ---- P = exp2(S - m), split to hi/lo A-fragments in-register ----
            float rs0 = 0.f, rs1 = 0.f;
            uint32_t ph[4][4], pl[4][4];
#pragma unroll
            for (int t = 0; t < 4; t++) {
#pragma unroll
                for (int hh = 0; hh < 2; hh++) {
                    const int nt = 2 * t + hh;
                    const float p0 = ex2(sacc[nt][0] - nm0);
                    const float p1 = ex2(sacc[nt][1] - nm0);
                    const float p2 = ex2(sacc[nt][2] - nm1);
                    const float p3 = ex2(sacc[nt][3] - nm1);
                    rs0 += p0 + p1; rs1 += p2 + p3;
                    split2(p0, p1, ph[t][2 * hh + 0], pl[t][2 * hh + 0]);
                    split2(p2, p3, ph[t][2 * hh + 1], pl[t][2 * hh + 1]);
                }
            }
            rs0 += __shfl_xor_sync(0xffffffffu, rs0, 1);
            rs0 += __shfl_xor_sync(0xffffffffu, rs0, 2);
            rs1 += __shfl_xor_sync(0xffffffffu, rs1, 1);
            rs1 += __shfl_xor_sync(0xffffffffu, rs1, 2);
            l0 += rs0; l1 += rs1;

            // ---- O += P V  (V via ldmatrix.trans; 3-pass hi/lo) ----
            const uint32_t vrow = lane & 15;
            const uint32_t vcg  = lane >> 4;
#pragma unroll
            for (int kt = 0; kt < 4; kt++) {
#pragma unroll
                for (int ntp = 0; ntp < 4; ntp++) {
                    const uint32_t off =
                        swz128((kt * 16 + vrow) * 128 + (2 * ntp + vcg) * 16);
                    uint32_t vbh[4], vbl[4];
                    ldm_x4t(vbh, VH + off);
                    ldm_x4t(vbl, VL + off);
                    mma16816(o[2 * ntp],     ph[kt], vbh + 0);
                    mma16816(o[2 * ntp],     ph[kt], vbl + 0);
                    mma16816(o[2 * ntp],     pl[kt], vbh + 0);
                    mma16816(o[2 * ntp + 1], ph[kt], vbh + 2);
                    mma16816(o[2 * ntp + 1], ph[kt], vbl + 2);
                    mma16816(o[2 * ntp + 1], pl[kt], vbh + 2);
                }
            }
        }
        __syncthreads();
    }

    // ---- normalize, write ctx directly in tiled/swizzled hi/lo format ----
    const float i0 = 1.f / l0;
    const float i1 = 1.f / l1;
    const int rb_t = b * 16 + qb;                       // 128-row tile index
    const uint32_t tbase = (uint32_t)(rb_t * NCHUNK + h) * TILE_B;
    const int rl0 = w * 16 + (lane >> 2);               // local row in tile
#pragma unroll
    for (int nt = 0; nt < 8; nt++) {
        const int col2 = (nt * 8 + (lane & 3) * 2) * 2; // byte col in 128B row
        uint32_t hi, lo;
        split2(o[nt][0] * i0, o[nt][1] * i0, hi, lo);
        uint32_t off = tbase + swz128((uint32_t)rl0 * 128 + col2);
        *(uint32_t*)((char*)ch + off) = hi;
        *(uint32_t*)((char*)cl + off) = lo;
        split2(o[nt][2] * i1, o[nt][3] * i1, hi, lo);
        off = tbase + swz128((uint32_t)(rl0 + 8) * 128 + col2);
        *(uint32_t*)((char*)ch + off) = hi;
        *(uint32_t*)((char*)cl + off) = lo;
    }
}

// ---------------------------------------------------------------------------
extern "C" void kernel_launch(void* const* d_in, const int* in_sizes, int n_in,
                              void* d_out, int out_size)
{
    const float* x  = (const float*)d_in[0];
    const float* Wq = (const float*)d_in[1];
    const float* Wk = (const float*)d_in[2];
    const float* Wv = (const float*)d_in[3];
    const float* Wo = (const float*)d_in[4];
    const float* bo = (const float*)d_in[5];
    float* out = (float*)d_out;

    __nv_bfloat16 *xh, *xl, *ch, *cl;
    __nv_bfloat16 *wqh, *wql, *wkh, *wkl, *wvh, *wvl, *woh, *wol;
    __nv_bfloat16 *qh, *ql, *kh, *kl, *vh, *vl;
    cudaGetSymbolAddress((void**)&xh,  g_xh);
    cudaGetSymbolAddress((void**)&xl,  g_xl);
    cudaGetSymbolAddress((void**)&ch,  g_ch);
    cudaGetSymbolAddress((void**)&cl,  g_cl);
    cudaGetSymbolAddress((void**)&wqh, g_wqh);
    cudaGetSymbolAddress((void**)&wql, g_wql);
    cudaGetSymbolAddress((void**)&wkh, g_wkh);
    cudaGetSymbolAddress((void**)&wkl, g_wkl);
    cudaGetSymbolAddress((void**)&wvh, g_wvh);
    cudaGetSymbolAddress((void**)&wvl, g_wvl);
    cudaGetSymbolAddress((void**)&woh, g_woh);
    cudaGetSymbolAddress((void**)&wol, g_wol);
    cudaGetSymbolAddress((void**)&qh,  g_qh);
    cudaGetSymbolAddress((void**)&ql,  g_ql);
    cudaGetSymbolAddress((void**)&kh,  g_kh);
    cudaGetSymbolAddress((void**)&kl,  g_kl);
    cudaGetSymbolAddress((void**)&vh,  g_vh);
    cudaGetSymbolAddress((void**)&vl,  g_vl);

    cudaFuncSetAttribute(gemm_mma, cudaFuncAttributeMaxDynamicSharedMemorySize,
                         GSM_BYTES);
    cudaFuncSetAttribute(flash_mma, cudaFuncAttributeMaxDynamicSharedMemorySize,
                         FSMEM);

    conv_act<<<4096, 256>>>(x, xh, xl);
    conv_w<<<512, 256>>>(Wq, wqh, wql);
    conv_w<<<512, 256>>>(Wk, wkh, wkl);
    conv_w<<<512, 256>>>(Wv, wvh, wvl);
    conv_w<<<512, 256>>>(Wo, woh, wol);

    dim3 gg(D_ / 128, NROW / 128);   // (8, 64)
    // Q gets softmax scale * log2(e) folded in; K,V plain.
    gemm_mma<<<gg, 256, GSM_BYTES>>>(xh, xl, wqh, wql, nullptr, nullptr,
                                     qh, ql, QSCALE);
    gemm_mma<<<gg, 256, GSM_BYTES>>>(xh, xl, wkh, wkl, nullptr, nullptr,
                                     kh, kl, 1.0f);
    gemm_mma<<<gg, 256, GSM_BYTES>>>(xh, xl, wvh, wvl, nullptr, nullptr,
                                     vh, vl, 1.0f);

    dim3 fg(S_ / 128, H_, B_);       // (16, 16, 4) = 1024 CTAs
    flash_mma<<<fg, 256, FSMEM>>>(qh, ql, kh, kl, vh, vl, ch, cl);

    gemm_mma<<<gg, 256, GSM_BYTES>>>(ch, cl, woh, wol, bo, out,
                                     nullptr, nullptr, 1.0f);
}